// round 3
// baseline (speedup 1.0000x reference)
#include <cuda_runtime.h>
#include <mma.h>
#include <cstddef>
#include <cstdint>

using namespace nvcuda;

// Problem constants
#define BATCH 128
#define HH 14
#define WW 14
#define CC 768
#define NHEAD 12
#define HDIM 64
#define HWSZ 196          // 14*14
#define C3 2304           // 3*C
#define MROWS 25088       // BATCH*HWSZ
#define NHEADS_TOTAL 1536 // BATCH*NHEAD

// Scratch buffers (device globals: no allocation allowed)
__device__ float g_qkv[(size_t)MROWS * C3]; // (B, HW, 3, NH, HD)
__device__ float g_att[(size_t)MROWS * CC]; // (B, HW, NH, HD)

// ---------------------------------------------------------------------------
// cp.async helpers
// ---------------------------------------------------------------------------
__device__ __forceinline__ void cpa16(void* s, const void* g) {
    uint32_t sa = (uint32_t)__cvta_generic_to_shared(s);
    asm volatile("cp.async.cg.shared.global [%0], [%1], 16;\n" ::"r"(sa), "l"(g));
}
__device__ __forceinline__ void cpa_commit() {
    asm volatile("cp.async.commit_group;\n" ::);
}
template <int N>
__device__ __forceinline__ void cpa_wait() {
    asm volatile("cp.async.wait_group %0;\n" ::"n"(N));
}

// ---------------------------------------------------------------------------
// Pipelined tf32 GEMM with fused bias: C = A(MxK) @ B(KxN) + bias (unchanged)
// ---------------------------------------------------------------------------
#define BM 128
#define BN 128
#define BK 32
#define ASTR 40
#define BSTR 136

#define GEMM_SMEM_BYTES (2 * BM * ASTR * 4 + 2 * BK * BSTR * 4 + 16 * BSTR * 4)

__device__ __forceinline__ void gemm_body(
    const float* __restrict__ A, const float* __restrict__ Bm,
    const float* __restrict__ bias, float* __restrict__ C,
    int M, int N, int K)
{
    extern __shared__ float smd[];
    float* As    = smd;
    float* Bs    = As + 2 * BM * ASTR;
    float* biasT = Bs + 2 * BK * BSTR;

    const int tid = threadIdx.x;
    const int m0 = blockIdx.y * BM;
    const int n0 = blockIdx.x * BN;

    for (int i = tid; i < 16 * BN; i += 256) {
        int rr = i >> 7, cc = i & 127;
        biasT[rr * BSTR + cc] = bias[n0 + cc];
    }
    __syncthreads();

    const int w  = tid >> 5;
    const int wm = w >> 2;
    const int wn = w & 3;

    wmma::fragment<wmma::accumulator, 16, 16, 8, float> acc[4][2];
#pragma unroll
    for (int i = 0; i < 4; i++)
#pragma unroll
        for (int j = 0; j < 2; j++)
            wmma::load_matrix_sync(acc[i][j], &biasT[wn * 32 + j * 16], BSTR,
                                   wmma::mem_row_major);

    const int arow = tid >> 3, ac4 = (tid & 7) * 4;
    const int brow = tid >> 5, bc4 = (tid & 31) * 4;

    const int T = K / BK;

    {
        const float* ag = &A[(size_t)(m0 + arow) * K + ac4];
        const float* bg = &Bm[(size_t)brow * N + n0 + bc4];
#pragma unroll
        for (int p = 0; p < 4; p++)
            cpa16(&As[(arow + p * 32) * ASTR + ac4], ag + (size_t)(p * 32) * K);
#pragma unroll
        for (int p = 0; p < 4; p++)
            cpa16(&Bs[(brow + p * 8) * BSTR + bc4], bg + (size_t)(p * 8) * N);
        cpa_commit();
    }

    for (int t = 0; t < T; t++) {
        if (t + 1 < T) {
            const int st = (t + 1) & 1;
            const int kt = (t + 1) * BK;
            const float* ag = &A[(size_t)(m0 + arow) * K + kt + ac4];
            const float* bg = &Bm[(size_t)(kt + brow) * N + n0 + bc4];
            float* asd = &As[st * BM * ASTR];
            float* bsd = &Bs[st * BK * BSTR];
#pragma unroll
            for (int p = 0; p < 4; p++)
                cpa16(&asd[(arow + p * 32) * ASTR + ac4], ag + (size_t)(p * 32) * K);
#pragma unroll
            for (int p = 0; p < 4; p++)
                cpa16(&bsd[(brow + p * 8) * BSTR + bc4], bg + (size_t)(p * 8) * N);
            cpa_commit();
            cpa_wait<1>();
        } else {
            cpa_wait<0>();
        }
        __syncthreads();

        const float* asrc = &As[(t & 1) * BM * ASTR];
        const float* bsrc = &Bs[(t & 1) * BK * BSTR];

#pragma unroll
        for (int kk = 0; kk < BK; kk += 8) {
            wmma::fragment<wmma::matrix_a, 16, 16, 8, wmma::precision::tf32,
                           wmma::row_major> af[4];
            wmma::fragment<wmma::matrix_b, 16, 16, 8, wmma::precision::tf32,
                           wmma::row_major> bf[2];
#pragma unroll
            for (int i = 0; i < 4; i++) {
                wmma::load_matrix_sync(af[i], &asrc[(wm * 64 + i * 16) * ASTR + kk], ASTR);
#pragma unroll
                for (int e = 0; e < af[i].num_elements; e++)
                    af[i].x[e] = wmma::__float_to_tf32(af[i].x[e]);
            }
#pragma unroll
            for (int j = 0; j < 2; j++) {
                wmma::load_matrix_sync(bf[j], &bsrc[kk * BSTR + wn * 32 + j * 16], BSTR);
#pragma unroll
                for (int e = 0; e < bf[j].num_elements; e++)
                    bf[j].x[e] = wmma::__float_to_tf32(bf[j].x[e]);
            }
#pragma unroll
            for (int i = 0; i < 4; i++)
#pragma unroll
                for (int j = 0; j < 2; j++)
                    wmma::mma_sync(acc[i][j], af[i], bf[j], acc[i][j]);
        }
        __syncthreads();
    }

#pragma unroll
    for (int i = 0; i < 4; i++)
#pragma unroll
        for (int j = 0; j < 2; j++)
            wmma::store_matrix_sync(
                &C[(size_t)(m0 + wm * 64 + i * 16) * N + n0 + wn * 32 + j * 16],
                acc[i][j], N, wmma::mem_row_major);
}

__global__ __launch_bounds__(256, 2) void gemm_qkv_kernel(
    const float* __restrict__ A, const float* __restrict__ Bm,
    const float* __restrict__ bias)
{
    gemm_body(A, Bm, bias, g_qkv, MROWS, C3, CC);
}

__global__ __launch_bounds__(256, 2) void gemm_proj_kernel(
    const float* __restrict__ Bm, const float* __restrict__ bias,
    float* __restrict__ C)
{
    gemm_body(g_att, Bm, bias, C, MROWS, CC, CC);
}

// ---------------------------------------------------------------------------
// Tensorized attention: one CTA per (batch, head), 256 threads (8 warps).
// Seq padded 196 -> 224 (14x16 tiles). K,V resident in smem. Queries
// processed in 32-row blocks: QK^T (wmma tf32) -> softmax+relpos (SIMT)
// -> PV (wmma tf32).
// ---------------------------------------------------------------------------
#define SP 224           // padded sequence
#define KSTR 68          // K/V/Q row stride (floats)
#define SSTR 232         // S block row stride (floats)

#define SM_K   (SP * KSTR)          // 15232
#define SM_V   (SP * KSTR)          // 15232
#define SM_RH  (27 * KSTR)          // 1836
#define SM_RW  (27 * KSTR)          // 1836
#define SM_Q   (32 * KSTR)          // 2176
#define SM_S   (32 * SSTR)          // 7424
#define SM_RB  (32 * 28)            // 896
#define ATTN_SMEM_FLOATS (SM_K + SM_V + SM_RH + SM_RW + SM_Q + SM_S + SM_RB)
#define ATTN_SMEM_BYTES (ATTN_SMEM_FLOATS * 4)

__global__ __launch_bounds__(256) void attn_kernel(
    const float* __restrict__ rph, const float* __restrict__ rpw)
{
    extern __shared__ float sm[];
    float* kS  = sm;
    float* vS  = kS + SM_K;
    float* RhS = vS + SM_V;
    float* RwS = RhS + SM_RH;
    float* qS  = RwS + SM_RW;
    float* sS  = qS + SM_Q;
    float* rb  = sS + SM_S;

    const int tid  = threadIdx.x;
    const int wid  = tid >> 5;
    const int head = blockIdx.x;
    const int b = head / NHEAD;
    const int h = head % NHEAD;

    const float* gbase = g_qkv + (size_t)b * HWSZ * C3 + h * HDIM;

    // Stage K, V (padded rows zeroed) and rel tables
    for (int i = tid; i < SP * HDIM; i += 256) {
        int j = i >> 6, d = i & 63;
        if (j < HWSZ) {
            const float* p = gbase + (size_t)j * C3 + d;
            kS[j * KSTR + d] = p[768];
            vS[j * KSTR + d] = p[1536];
        } else {
            kS[j * KSTR + d] = 0.f;
            vS[j * KSTR + d] = 0.f;
        }
    }
    for (int i = tid; i < 27 * HDIM; i += 256) {
        int r = i >> 6, d = i & 63;
        RhS[r * KSTR + d] = rph[i];
        RwS[r * KSTR + d] = rpw[i];
    }

    for (int blk = 0; blk < 7; blk++) {
        const int r0 = blk * 32;
        __syncthreads();  // previous block fully done (incl. O copy from qS)

        // --- Stage Q block (32 x 64), zero for invalid rows ---
        for (int i = tid; i < 32 * HDIM / 4; i += 256) {
            int rr = i >> 4, c4 = (i & 15) * 4;
            int r = r0 + rr;
            float4 v = make_float4(0.f, 0.f, 0.f, 0.f);
            if (r < HWSZ)
                v = *(const float4*)(gbase + (size_t)r * C3 + c4);
            *(float4*)(qS + rr * KSTR + c4) = v;
        }
        __syncthreads();

        // --- rel-pos dots: rb[rr][0..13]=relh, rb[rr][14..27]=relw ---
        for (int t = tid; t < 32 * 28; t += 256) {
            int rr = t / 28, wch = t % 28;
            int r = r0 + rr;
            int row;
            const float* tab;
            if (wch < 14) { row = r / 14 - wch + 13;        tab = RhS; }
            else          { row = r % 14 - (wch - 14) + 13; tab = RwS; }
            row = min(max(row, 0), 26);  // clamp for invalid rows
            const float* qp = qS + rr * KSTR;
            const float* tp = tab + row * KSTR;
            float s = 0.f;
#pragma unroll
            for (int d = 0; d < 64; d++) s += qp[d] * tp[d];
            rb[rr * 28 + wch] = s;
        }

        // --- QK^T: 2x14 = 28 tiles of 16x16, k=64 in 8 steps ---
        for (int t = wid; t < 28; t += 8) {
            const int mt = t / 14, nt = t % 14;
            wmma::fragment<wmma::accumulator, 16, 16, 8, float> acc;
            wmma::fill_fragment(acc, 0.f);
#pragma unroll
            for (int ks = 0; ks < 8; ks++) {
                wmma::fragment<wmma::matrix_a, 16, 16, 8, wmma::precision::tf32,
                               wmma::row_major> af;
                wmma::fragment<wmma::matrix_b, 16, 16, 8, wmma::precision::tf32,
                               wmma::col_major> bf;
                wmma::load_matrix_sync(af, &qS[mt * 16 * KSTR + ks * 8], KSTR);
                wmma::load_matrix_sync(bf, &kS[nt * 16 * KSTR + ks * 8], KSTR);
#pragma unroll
                for (int e = 0; e < af.num_elements; e++)
                    af.x[e] = wmma::__float_to_tf32(af.x[e]);
#pragma unroll
                for (int e = 0; e < bf.num_elements; e++)
                    bf.x[e] = wmma::__float_to_tf32(bf.x[e]);
                wmma::mma_sync(acc, af, bf, acc);
            }
            wmma::store_matrix_sync(&sS[mt * 16 * SSTR + nt * 16], acc, SSTR,
                                    wmma::mem_row_major);
        }
        __syncthreads();

        // --- Softmax in place (8 threads per row, 28 cols each) ---
        {
            const int rr = tid >> 3, sub = tid & 7;
            const float* rbr = rb + rr * 28;
            float vals[28];
            float m = -1e30f;
#pragma unroll
            for (int i = 0; i < 28; i++) {
                int j = sub + i * 8;
                float s = -1e30f;
                if (j < HWSZ)
                    s = sS[rr * SSTR + j] * 0.125f + rbr[j / 14] + rbr[14 + j % 14];
                vals[i] = s;
                m = fmaxf(m, s);
            }
#pragma unroll
            for (int o = 4; o > 0; o >>= 1)
                m = fmaxf(m, __shfl_xor_sync(0xffffffffu, m, o));
            float lsum = 0.f;
#pragma unroll
            for (int i = 0; i < 28; i++) {
                float e = __expf(vals[i] - m);
                vals[i] = e;
                lsum += e;
            }
#pragma unroll
            for (int o = 4; o > 0; o >>= 1)
                lsum += __shfl_xor_sync(0xffffffffu, lsum, o);
            float inv = 1.f / lsum;
#pragma unroll
            for (int i = 0; i < 28; i++) {
                int j = sub + i * 8;
                sS[rr * SSTR + j] = vals[i] * inv;
            }
        }
        __syncthreads();

        // --- PV: 2x4 tiles of 16x16, k=224 in 28 steps; stage O into qS ---
        {
            const int mt = wid >> 2, nt = wid & 3;
            wmma::fragment<wmma::accumulator, 16, 16, 8, float> acc;
            wmma::fill_fragment(acc, 0.f);
#pragma unroll 4
            for (int ks = 0; ks < 28; ks++) {
                wmma::fragment<wmma::matrix_a, 16, 16, 8, wmma::precision::tf32,
                               wmma::row_major> af;
                wmma::fragment<wmma::matrix_b, 16, 16, 8, wmma::precision::tf32,
                               wmma::row_major> bf;
                wmma::load_matrix_sync(af, &sS[mt * 16 * SSTR + ks * 8], SSTR);
                wmma::load_matrix_sync(bf, &vS[ks * 8 * KSTR + nt * 16], KSTR);
#pragma unroll
                for (int e = 0; e < af.num_elements; e++)
                    af.x[e] = wmma::__float_to_tf32(af.x[e]);
#pragma unroll
                for (int e = 0; e < bf.num_elements; e++)
                    bf.x[e] = wmma::__float_to_tf32(bf.x[e]);
                wmma::mma_sync(acc, af, bf, acc);
            }
            wmma::store_matrix_sync(&qS[mt * 16 * KSTR + nt * 16], acc, KSTR,
                                    wmma::mem_row_major);
        }
        __syncthreads();

        // --- Copy valid O rows to g_att ---
        float* gout = g_att + ((size_t)b * HWSZ + r0) * CC + h * HDIM;
        for (int i = tid; i < 32 * HDIM / 4; i += 256) {
            int rr = i >> 4, c4 = (i & 15) * 4;
            if (r0 + rr < HWSZ)
                *(float4*)(gout + (size_t)rr * CC + c4) =
                    *(const float4*)(qS + rr * KSTR + c4);
        }
    }
}

// ---------------------------------------------------------------------------
extern "C" void kernel_launch(void* const* d_in, const int* in_sizes, int n_in,
                              void* d_out, int out_size)
{
    const float* x      = (const float*)d_in[0]; // (25088, 768)
    const float* w_qkv  = (const float*)d_in[1]; // (768, 2304)
    const float* b_qkv  = (const float*)d_in[2]; // (2304,)
    const float* rph    = (const float*)d_in[3]; // (27, 64)
    const float* rpw    = (const float*)d_in[4]; // (27, 64)
    const float* w_proj = (const float*)d_in[5]; // (768, 768)
    const float* b_proj = (const float*)d_in[6]; // (768,)
    float* out = (float*)d_out;                  // (25088, 768)

    cudaFuncSetAttribute(gemm_qkv_kernel,
                         cudaFuncAttributeMaxDynamicSharedMemorySize,
                         GEMM_SMEM_BYTES);
    cudaFuncSetAttribute(gemm_proj_kernel,
                         cudaFuncAttributeMaxDynamicSharedMemorySize,
                         GEMM_SMEM_BYTES);
    cudaFuncSetAttribute(attn_kernel,
                         cudaFuncAttributeMaxDynamicSharedMemorySize,
                         ATTN_SMEM_BYTES);

    dim3 g1(C3 / BN, MROWS / BM);
    gemm_qkv_kernel<<<g1, 256, GEMM_SMEM_BYTES>>>(x, w_qkv, b_qkv);

    attn_kernel<<<NHEADS_TOTAL, 256, ATTN_SMEM_BYTES>>>(rph, rpw);

    dim3 g2(CC / BN, MROWS / BM);
    gemm_proj_kernel<<<g2, 256, GEMM_SMEM_BYTES>>>(w_proj, b_proj, out);
}